// round 1
// baseline (speedup 1.0000x reference)
#include <cuda_runtime.h>
#include <cstdint>

// Problem constants
#define PP   4096
#define BB   32
#define FEAT 512
#define ATTN 512
#define NH   8
#define HD   64
#define MROWS (PP*BB)          // 131072

// ---------------- scratch (device globals; no allocations allowed) ----------
__device__ float g_u[BB * ATTN];          // folded hid term + biases, [b][h*64+j]
__device__ float g_M2[FEAT * ATTN];       // Wa folded with Wa2, [k][h*64+j]
__device__ float g_scores[MROWS * NH];    // [p*32+b][h]
__device__ float g_weights[MROWS * NH];
__device__ float g_smax[BB * NH];
__device__ float g_ssum[BB * NH];
#define PCH 16                             // p-chunks for xbar partials
__device__ float g_partial[PCH * BB * NH * FEAT]; // 16*32*8*512 = 2M floats

// ---------------- helpers ----------------------------------------------------
__device__ __forceinline__ float tf32r(float x) {
    uint32_t u;
    asm("cvt.rna.tf32.f32 %0, %1;" : "=r"(u) : "f"(x));
    return __uint_as_float(u);
}

__device__ __forceinline__ void mma_tf32(float* d, const uint32_t* a, const uint32_t* b) {
    asm volatile(
        "mma.sync.aligned.m16n8k8.row.col.f32.tf32.tf32.f32 "
        "{%0,%1,%2,%3}, {%4,%5,%6,%7}, {%8,%9}, {%0,%1,%2,%3};"
        : "+f"(d[0]), "+f"(d[1]), "+f"(d[2]), "+f"(d[3])
        : "r"(a[0]), "r"(a[1]), "r"(a[2]), "r"(a[3]), "r"(b[0]), "r"(b[1]));
}

// tanh(x) = 1 - 2/(exp(2x)+1); 2 MUFU + few FMA, err ~1e-6, handles +-inf.
__device__ __forceinline__ float ftanh(float x) {
    float e = __expf(2.0f * x);
    return 1.0f - __fdividef(2.0f, e + 1.0f);
}

// ---------------- K0a: per-b hid projection + fold biases into g_u ----------
__global__ void k_prep_u(const float* __restrict__ lh, const float* __restrict__ Ua,
                         const float* __restrict__ Ua_b, const float* __restrict__ Ua2,
                         const float* __restrict__ Ua2_b, const float* __restrict__ Wa_b,
                         const float* __restrict__ Wa2, const float* __restrict__ Wa2_b) {
    __shared__ float sh_lh[FEAT];
    __shared__ float sh_hid[ATTN];
    int b = blockIdx.x, t = threadIdx.x;
    sh_lh[t] = lh[b * FEAT + t];
    __syncthreads();
    float acc = Ua_b[t];
    for (int k = 0; k < FEAT; k++) acc += sh_lh[k] * Ua[k * ATTN + t];
    sh_hid[t] = acc;
    __syncthreads();
    int h = t >> 6, j = t & 63;
    float acc2 = Ua2_b[j] + Wa2_b[j];
    for (int d = 0; d < HD; d++) {
        acc2 += sh_hid[h * HD + d] * Ua2[d * HD + j];
        acc2 += Wa_b[h * HD + d] * Wa2[d * HD + j];
    }
    g_u[b * ATTN + t] = acc2;
}

// ---------------- K0b: M2[k][h*64+j] = sum_d Wa[k][h*64+d]*Wa2[d][j] --------
__global__ void k_prep_M2(const float* __restrict__ Wa, const float* __restrict__ Wa2) {
    __shared__ float sh_wa[ATTN];
    __shared__ float sh_w2[HD * HD];
    int k = blockIdx.x, t = threadIdx.x;
    sh_wa[t] = Wa[k * ATTN + t];
    for (int i = t; i < HD * HD; i += blockDim.x) sh_w2[i] = Wa2[i];
    __syncthreads();
    int h = t >> 6, j = t & 63;
    float acc = 0.f;
    #pragma unroll 8
    for (int d = 0; d < HD; d++) acc += sh_wa[h * HD + d] * sh_w2[d * HD + j];
    g_M2[k * ATTN + t] = acc;
}

// ---------------- K1: fused tf32 GEMM + tanh + va-dot -> scores --------------
// T = X @ M2 (only head h's 64 columns per CTA), fused epilogue produces
// scores[row][h]. CTA tile 128x64, K-chunk 32, 8 warps (4x2), m16n8k8 tf32.
#define BM 128
#define BN 64
#define BKC 32
__global__ void __launch_bounds__(256) k_scores(const float* __restrict__ X,
                                                const float* __restrict__ va_w,
                                                const float* __restrict__ va_b) {
    __shared__ float As[BM][BKC + 4];
    __shared__ float Bs[BN][BKC + 4];
    __shared__ float Us[BB * HD];
    __shared__ float Va[HD];
    __shared__ float Psum[BM][2];

    int h = blockIdx.x;           // 0..7  (fastest -> A-tile reuse in L2)
    int mtile = blockIdx.y;       // 0..1023
    int rowbase = mtile * BM;
    int tid = threadIdx.x;
    int warp = tid >> 5, lane = tid & 31;
    int wm = warp >> 1, wn = warp & 1;
    int g = lane >> 2, tq = lane & 3;

    for (int i = tid; i < BB * HD; i += 256) {
        int b = i >> 6, j = i & 63;
        Us[i] = g_u[b * ATTN + h * HD + j];
    }
    if (tid < HD) Va[tid] = va_w[tid];

    float acc[2][4][4];
    #pragma unroll
    for (int mi = 0; mi < 2; mi++)
        #pragma unroll
        for (int ni = 0; ni < 4; ni++)
            #pragma unroll
            for (int e = 0; e < 4; e++) acc[mi][ni][e] = 0.f;

    const float* Ag = X + (size_t)rowbase * FEAT;

    for (int kb = 0; kb < FEAT; kb += BKC) {
        __syncthreads();
        // stage A: 128x32 fp32 -> tf32-rounded
        #pragma unroll
        for (int it = 0; it < 4; it++) {
            int fid = tid + 256 * it;              // 0..1023 float4s
            int row = fid >> 3;
            int kk = (fid & 7) * 4;
            float4 v = *reinterpret_cast<const float4*>(Ag + (size_t)row * FEAT + kb + kk);
            v.x = tf32r(v.x); v.y = tf32r(v.y); v.z = tf32r(v.z); v.w = tf32r(v.w);
            *reinterpret_cast<float4*>(&As[row][kk]) = v;
        }
        // stage B (head slice of M2), transposed into [n][k]
        #pragma unroll
        for (int it = 0; it < 2; it++) {
            int fid = tid + 256 * it;              // 0..511 float4s
            int krow = fid >> 4;                   // 0..31
            int nn = (fid & 15) * 4;
            float4 v = *reinterpret_cast<const float4*>(
                g_M2 + (size_t)(kb + krow) * ATTN + h * HD + nn);
            Bs[nn + 0][krow] = tf32r(v.x);
            Bs[nn + 1][krow] = tf32r(v.y);
            Bs[nn + 2][krow] = tf32r(v.z);
            Bs[nn + 3][krow] = tf32r(v.w);
        }
        __syncthreads();
        #pragma unroll
        for (int ks = 0; ks < 4; ks++) {
            int k0 = ks * 8;
            uint32_t afr[2][4], bfr[4][2];
            #pragma unroll
            for (int mi = 0; mi < 2; mi++) {
                int r0 = wm * 32 + mi * 16;
                afr[mi][0] = __float_as_uint(As[r0 + g][k0 + tq]);
                afr[mi][1] = __float_as_uint(As[r0 + g + 8][k0 + tq]);
                afr[mi][2] = __float_as_uint(As[r0 + g][k0 + tq + 4]);
                afr[mi][3] = __float_as_uint(As[r0 + g + 8][k0 + tq + 4]);
            }
            #pragma unroll
            for (int ni = 0; ni < 4; ni++) {
                int n0 = wn * 32 + ni * 8;
                bfr[ni][0] = __float_as_uint(Bs[n0 + g][k0 + tq]);
                bfr[ni][1] = __float_as_uint(Bs[n0 + g][k0 + tq + 4]);
            }
            #pragma unroll
            for (int mi = 0; mi < 2; mi++)
                #pragma unroll
                for (int ni = 0; ni < 4; ni++)
                    mma_tf32(acc[mi][ni], afr[mi], bfr[ni]);
        }
    }

    // epilogue: += u, tanh, dot with va -> per-row partial sums
    float rs[2][2] = {{0.f, 0.f}, {0.f, 0.f}};
    #pragma unroll
    for (int mi = 0; mi < 2; mi++) {
        int r0 = wm * 32 + mi * 16 + g;
        int bA = r0 & 31, bB = (r0 + 8) & 31;
        #pragma unroll
        for (int ni = 0; ni < 4; ni++) {
            int j0 = wn * 32 + ni * 8 + 2 * tq;
            float vA0 = acc[mi][ni][0] + Us[bA * HD + j0];
            float vA1 = acc[mi][ni][1] + Us[bA * HD + j0 + 1];
            float vB0 = acc[mi][ni][2] + Us[bB * HD + j0];
            float vB1 = acc[mi][ni][3] + Us[bB * HD + j0 + 1];
            rs[mi][0] += ftanh(vA0) * Va[j0] + ftanh(vA1) * Va[j0 + 1];
            rs[mi][1] += ftanh(vB0) * Va[j0] + ftanh(vB1) * Va[j0 + 1];
        }
    }
    #pragma unroll
    for (int mi = 0; mi < 2; mi++)
        #pragma unroll
        for (int hh = 0; hh < 2; hh++) {
            rs[mi][hh] += __shfl_xor_sync(0xffffffff, rs[mi][hh], 1);
            rs[mi][hh] += __shfl_xor_sync(0xffffffff, rs[mi][hh], 2);
        }
    if (tq == 0) {
        #pragma unroll
        for (int mi = 0; mi < 2; mi++) {
            Psum[wm * 32 + mi * 16 + g][wn]     = rs[mi][0];
            Psum[wm * 32 + mi * 16 + g + 8][wn] = rs[mi][1];
        }
    }
    __syncthreads();
    if (tid < BM) {
        float s = Psum[tid][0] + Psum[tid][1] + va_b[0];
        int row = rowbase + tid;
        g_scores[(size_t)row * NH + h] = s;
    }
}

// ---------------- K2a: per-(b,h) max and sum(exp) ----------------------------
__global__ void k_stats() {
    __shared__ float red[256];
    int bh = blockIdx.x, t = threadIdx.x;
    float v[16];
    float mx = -1e30f;
    #pragma unroll
    for (int i = 0; i < 16; i++) {
        v[i] = g_scores[(size_t)(i * 256 + t) * 256 / 256 * 256 + (size_t)(i * 256 + t) * 0 + (size_t)(i * 256 + t) * 256 + bh - (size_t)(i * 256 + t) * 256 + (size_t)(i * 256 + t) * 256 + bh - bh + (size_t)(i * 256 + t) * 256 + bh - (size_t)(i * 256 + t) * 256];
    }
    // (rewritten cleanly below; keep simple form)
    #pragma unroll
    for (int i = 0; i < 16; i++) {
        v[i] = g_scores[(size_t)(i * 256 + t) * 256 + bh];
        mx = fmaxf(mx, v[i]);
    }
    red[t] = mx; __syncthreads();
    for (int s = 128; s > 0; s >>= 1) {
        if (t < s) red[t] = fmaxf(red[t], red[t + s]);
        __syncthreads();
    }
    mx = red[0]; __syncthreads();
    float sum = 0.f;
    #pragma unroll
    for (int i = 0; i < 16; i++) sum += __expf(v[i] - mx);
    red[t] = sum; __syncthreads();
    for (int s = 128; s > 0; s >>= 1) {
        if (t < s) red[t] += red[t + s];
        __syncthreads();
    }
    if (t == 0) { g_smax[bh] = mx; g_ssum[bh] = red[0]; }
}

// ---------------- K2b: normalize -> weights + head-mean output --------------
__global__ void k_weights(float* __restrict__ out_w) {
    int idx = blockIdx.x * 256 + threadIdx.x;   // (p*32+b) < 131072
    int b = idx & 31;
    float sc[8];
    *reinterpret_cast<float4*>(&sc[0]) = *reinterpret_cast<const float4*>(&g_scores[(size_t)idx * 8]);
    *reinterpret_cast<float4*>(&sc[4]) = *reinterpret_cast<const float4*>(&g_scores[(size_t)idx * 8 + 4]);
    float w[8], tot = 0.f;
    #pragma unroll
    for (int h = 0; h < 8; h++) {
        float m = g_smax[b * 8 + h], s = g_ssum[b * 8 + h];
        w[h] = __fdividef(__expf(sc[h] - m), s);
        tot += w[h];
    }
    *reinterpret_cast<float4*>(&g_weights[(size_t)idx * 8])     = *reinterpret_cast<float4*>(&w[0]);
    *reinterpret_cast<float4*>(&g_weights[(size_t)idx * 8 + 4]) = *reinterpret_cast<float4*>(&w[4]);
    out_w[idx] = tot * 0.125f;
}

// ---------------- K3: partial xbar = sum_p w[p,b,h]*X[p,b,f] -----------------
__global__ void k_xbar(const float* __restrict__ X) {
    __shared__ float ws[256 * 8];
    int b = blockIdx.x, fc = blockIdx.y, pc = blockIdx.z;
    int tid = threadIdx.x;                 // 256
    int f = fc * 256 + tid;
    int p0 = pc * 256;
    #pragma unroll
    for (int it = 0; it < 2; it++) {
        int fid = tid + 256 * it;          // 0..511 float4s
        int pp = fid >> 1, h4 = (fid & 1) * 4;
        *reinterpret_cast<float4*>(&ws[pp * 8 + h4]) =
            *reinterpret_cast<const float4*>(&g_weights[((size_t)(p0 + pp) * BB + b) * 8 + h4]);
    }
    __syncthreads();
    float acc[8];
    #pragma unroll
    for (int h = 0; h < 8; h++) acc[h] = 0.f;
    for (int p = 0; p < 256; p++) {
        float x = X[((size_t)(p0 + p) * BB + b) * FEAT + f];
        float4 w0 = *reinterpret_cast<float4*>(&ws[p * 8]);
        float4 w1 = *reinterpret_cast<float4*>(&ws[p * 8 + 4]);
        acc[0] += w0.x * x; acc[1] += w0.y * x; acc[2] += w0.z * x; acc[3] += w0.w * x;
        acc[4] += w1.x * x; acc[5] += w1.y * x; acc[6] += w1.z * x; acc[7] += w1.w * x;
    }
    #pragma unroll
    for (int h = 0; h < 8; h++)
        g_partial[(((size_t)pc * BB + b) * NH + h) * FEAT + f] = acc[h];
}

// ---------------- K4: context = xbar @ Wa_slice + Wa_b -----------------------
__global__ void k_context(const float* __restrict__ Wa, const float* __restrict__ Wa_b,
                          float* __restrict__ out) {
    __shared__ float xb[NH * FEAT];        // 16KB
    int b = blockIdx.x, t = threadIdx.x;   // 512 threads
    for (int i = t; i < NH * FEAT; i += 512) {
        float s = 0.f;
        #pragma unroll
        for (int pc = 0; pc < PCH; pc++) s += g_partial[((size_t)pc * BB + b) * (NH * FEAT) + i];
        xb[i] = s;
    }
    __syncthreads();
    int h = t >> 6;
    float acc = Wa_b[t];
    for (int k = 0; k < FEAT; k++) acc += xb[h * FEAT + k] * Wa[k * ATTN + t];
    out[b * ATTN + t] = acc;
}

// ---------------- launch -----------------------------------------------------
extern "C" void kernel_launch(void* const* d_in, const int* in_sizes, int n_in,
                              void* d_out, int out_size) {
    const float* lh    = (const float*)d_in[0];
    const float* X     = (const float*)d_in[1];
    const float* Wa_w  = (const float*)d_in[2];
    const float* Wa_b  = (const float*)d_in[3];
    const float* Ua_w  = (const float*)d_in[4];
    const float* Ua_b  = (const float*)d_in[5];
    const float* Wa2_w = (const float*)d_in[6];
    const float* Wa2_b = (const float*)d_in[7];
    const float* Ua2_w = (const float*)d_in[8];
    const float* Ua2_b = (const float*)d_in[9];
    const float* va_w  = (const float*)d_in[10];
    const float* va_b  = (const float*)d_in[11];
    float* out = (float*)d_out;            // [0,16384): context, [16384,147456): weight

    k_prep_u<<<BB, 512>>>(lh, Ua_w, Ua_b, Ua2_w, Ua2_b, Wa_b, Wa2_w, Wa2_b);
    k_prep_M2<<<FEAT, 512>>>(Wa_w, Wa2_w);
    k_scores<<<dim3(NH, MROWS / BM), 256>>>(X, va_w, va_b);
    k_stats<<<BB * NH, 256>>>();
    k_weights<<<MROWS / 256, 256>>>(out + BB * ATTN);
    k_xbar<<<dim3(BB, 2, PCH), 256>>>(X);
    k_context<<<BB, 512>>>(Wa_w, Wa_b, out);
}

// round 3
// speedup vs baseline: 1.4367x; 1.4367x over previous
#include <cuda_runtime.h>
#include <cstdint>

// Problem constants
#define PP   4096
#define BB   32
#define FEAT 512
#define ATTN 512
#define NH   8
#define HD   64
#define MROWS (PP*BB)          // 131072

// ---------------- scratch (device globals; no allocations allowed) ----------
__device__ float g_u[BB * ATTN];          // folded hid term + biases, [b][h*64+j]
__device__ float g_M2T[ATTN * FEAT];      // (Wa@Wa2) transposed: [n][k]
__device__ float g_scores[MROWS * NH];    // [p*32+b][h]
__device__ float g_weights[MROWS * NH];
__device__ float g_smax[BB * NH];
__device__ float g_ssum[BB * NH];
#define PCH 16
__device__ float g_partial[PCH * BB * NH * FEAT]; // 2M floats

// ---------------- helpers ----------------------------------------------------
__device__ __forceinline__ float tf32r(float x) {
    uint32_t u;
    asm("cvt.rna.tf32.f32 %0, %1;" : "=r"(u) : "f"(x));
    return __uint_as_float(u);
}
__device__ __forceinline__ uint32_t s2u(const void* p) {
    uint32_t a;
    asm("{ .reg .u64 t; cvta.to.shared.u64 t, %1; cvt.u32.u64 %0, t; }" : "=r"(a) : "l"(p));
    return a;
}
__device__ __forceinline__ void cp16(uint32_t d, const void* s) {
    asm volatile("cp.async.cg.shared.global [%0], [%1], 16;" :: "r"(d), "l"(s));
}
__device__ __forceinline__ void cp_commit() { asm volatile("cp.async.commit_group;" ::: "memory"); }

__device__ __forceinline__ void mma_tf32(float* d, const uint32_t* a, const uint32_t* b) {
    asm volatile(
        "mma.sync.aligned.m16n8k8.row.col.f32.tf32.tf32.f32 "
        "{%0,%1,%2,%3}, {%4,%5,%6,%7}, {%8,%9}, {%0,%1,%2,%3};"
        : "+f"(d[0]), "+f"(d[1]), "+f"(d[2]), "+f"(d[3])
        : "r"(a[0]), "r"(a[1]), "r"(a[2]), "r"(a[3]), "r"(b[0]), "r"(b[1]));
}
__device__ __forceinline__ float tanhfast(float x) {
    float t;
    asm("tanh.approx.f32 %0, %1;" : "=f"(t) : "f"(x));
    return t;
}

// ---------------- K0a: per-b hid projection + fold biases into g_u ----------
__global__ void k_prep_u(const float* __restrict__ lh, const float* __restrict__ Ua,
                         const float* __restrict__ Ua_b, const float* __restrict__ Ua2,
                         const float* __restrict__ Ua2_b, const float* __restrict__ Wa_b,
                         const float* __restrict__ Wa2, const float* __restrict__ Wa2_b) {
    __shared__ float sh_lh[FEAT];
    __shared__ float sh_hid[ATTN];
    int b = blockIdx.x, t = threadIdx.x;
    sh_lh[t] = lh[b * FEAT + t];
    __syncthreads();
    float acc = Ua_b[t];
    for (int k = 0; k < FEAT; k++) acc += sh_lh[k] * Ua[k * ATTN + t];
    sh_hid[t] = acc;
    __syncthreads();
    int h = t >> 6, j = t & 63;
    float acc2 = Ua2_b[j] + Wa2_b[j];
    for (int d = 0; d < HD; d++) {
        acc2 += sh_hid[h * HD + d] * Ua2[d * HD + j];
        acc2 += Wa_b[h * HD + d] * Wa2[d * HD + j];
    }
    g_u[b * ATTN + t] = acc2;
}

// ---------------- K0b: g_M2T[n][k] = sum_d Wa[k][h*64+d]*Wa2[d][j], n=h*64+j -
__global__ void k_prep_B(const float* __restrict__ Wa, const float* __restrict__ Wa2) {
    __shared__ float sh_wa[ATTN];
    __shared__ float sh_w2[HD * HD];
    int k = blockIdx.x, t = threadIdx.x;
    sh_wa[t] = Wa[k * ATTN + t];
    for (int i = t; i < HD * HD; i += blockDim.x) sh_w2[i] = Wa2[i];
    __syncthreads();
    int h = t >> 6, j = t & 63;
    float acc = 0.f;
    #pragma unroll 8
    for (int d = 0; d < HD; d++) acc += sh_wa[h * HD + d] * sh_w2[d * HD + j];
    g_M2T[(size_t)t * FEAT + k] = tf32r(acc);   // transposed, tf32-prerounded
}

// ---------------- K1: pipelined tf32 mma.sync GEMM + tanh + va-dot ----------
// CTA tile 128 x 256 (4 heads), 512 threads (16 warps, 4x4), warp tile 32x64.
// K streamed in 16 chunks of 32, 3-stage cp.async pipeline.
#define BK 32
#define ROWPAD 36                        // 32 + 4 floats, conflict-free LDS
#define STAGE_BYTES (128*ROWPAD*4 + 256*ROWPAD*4)   // 18432 + 36864 = 55296
#define US_OFF (3*STAGE_BYTES)           // 165888
#define VA_OFF (US_OFF + 32*256*4)       // 198656
#define SMEM_TOTAL (VA_OFF + 256*4)      // 199680

__device__ __forceinline__ void prefetch2(int c, int s, uint32_t smem32,
                                          const char* Xrow, const char* Bt, int tid) {
    uint32_t sa = smem32 + s * STAGE_BYTES;
    uint32_t sb = sa + 128 * ROWPAD * 4;
    const char* Asrc = Xrow + c * 128;
    #pragma unroll
    for (int it = 0; it < 2; it++) {
        int i = tid + it * 512;            // 0..1023 A granules (16B)
        int row = i >> 3, q = i & 7;
        cp16(sa + row * (ROWPAD * 4) + q * 16, Asrc + (size_t)row * 2048 + q * 16);
    }
    const char* Bsrc = Bt + c * 128;
    #pragma unroll
    for (int it = 0; it < 4; it++) {
        int i = tid + it * 512;            // 0..2047 B granules (16B)
        int n = i >> 3, q = i & 7;
        cp16(sb + n * (ROWPAD * 4) + q * 16, Bsrc + (size_t)n * 2048 + q * 16);
    }
    cp_commit();
}

__global__ void __launch_bounds__(512, 1) k_scores2(const float* __restrict__ X,
                                                    const float* __restrict__ va_w,
                                                    const float* __restrict__ va_b) {
    extern __shared__ char smem[];
    uint32_t smem32 = s2u(smem);
    int tid = threadIdx.x;
    int warp = tid >> 5, lane = tid & 31;
    int wm = warp >> 2, wn = warp & 3;      // 4x4 warp grid
    int g = lane >> 2, tq = lane & 3;
    int hg = blockIdx.x;                    // head group (0..1): heads hg*4..hg*4+3
    int rowbase = blockIdx.y * 128;

    // stage Us (u for this head group) and Va
    float* Us = reinterpret_cast<float*>(smem + US_OFF);     // [32][256]
    float* Va = reinterpret_cast<float*>(smem + VA_OFF);     // [256]
    for (int i = tid; i < 32 * 256; i += 512) {
        int b = i >> 8, n = i & 255;
        Us[i] = g_u[b * ATTN + hg * 256 + n];
    }
    if (tid < 256) Va[tid] = va_w[tid & 63];

    const char* Xrow = reinterpret_cast<const char*>(X) + (size_t)rowbase * 2048;
    const char* Bt = reinterpret_cast<const char*>(g_M2T) + (size_t)hg * 256 * 2048;

    prefetch2(0, 0, smem32, Xrow, Bt, tid);
    prefetch2(1, 1, smem32, Xrow, Bt, tid);
    prefetch2(2, 2, smem32, Xrow, Bt, tid);

    float acc[2][8][4];
    #pragma unroll
    for (int mi = 0; mi < 2; mi++)
        #pragma unroll
        for (int ni = 0; ni < 8; ni++)
            #pragma unroll
            for (int e = 0; e < 4; e++) acc[mi][ni][e] = 0.f;

    int s = 0;
    #pragma unroll 1
    for (int c = 0; c < 16; c++) {
        asm volatile("cp.async.wait_group 2;" ::: "memory");
        __syncthreads();
        const float* As = reinterpret_cast<const float*>(smem + s * STAGE_BYTES);
        const float* Bs = As + 128 * ROWPAD;
        #pragma unroll
        for (int ks = 0; ks < 4; ks++) {
            int k0 = ks * 8;
            uint32_t afr[2][4], bfr[8][2];
            #pragma unroll
            for (int mi = 0; mi < 2; mi++) {
                int r0 = wm * 32 + mi * 16;
                afr[mi][0] = __float_as_uint(As[(r0 + g) * ROWPAD + k0 + tq]);
                afr[mi][1] = __float_as_uint(As[(r0 + g + 8) * ROWPAD + k0 + tq]);
                afr[mi][2] = __float_as_uint(As[(r0 + g) * ROWPAD + k0 + tq + 4]);
                afr[mi][3] = __float_as_uint(As[(r0 + g + 8) * ROWPAD + k0 + tq + 4]);
            }
            #pragma unroll
            for (int ni = 0; ni < 8; ni++) {
                int n0 = wn * 64 + ni * 8;
                bfr[ni][0] = __float_as_uint(Bs[(n0 + g) * ROWPAD + k0 + tq]);
                bfr[ni][1] = __float_as_uint(Bs[(n0 + g) * ROWPAD + k0 + tq + 4]);
            }
            #pragma unroll
            for (int mi = 0; mi < 2; mi++)
                #pragma unroll
                for (int ni = 0; ni < 8; ni++)
                    mma_tf32(acc[mi][ni], afr[mi], bfr[ni]);
        }
        __syncthreads();
        if (c < 13) prefetch2(c + 3, s, smem32, Xrow, Bt, tid);
        else        cp_commit();           // keep group count aligned for wait 2
        s = (s == 2) ? 0 : s + 1;
    }

    // epilogue: warp wn owns head hg*4+wn entirely (cols wn*64..wn*64+63)
    float rs[2][2] = {{0.f, 0.f}, {0.f, 0.f}};
    #pragma unroll
    for (int mi = 0; mi < 2; mi++) {
        int rA = mi * 16 + g;               // row & 31 (wm*32 drops out)
        #pragma unroll
        for (int ni = 0; ni < 8; ni++) {
            int j0 = wn * 64 + ni * 8 + 2 * tq;
            float v00 = acc[mi][ni][0] + Us[rA * 256 + j0];
            float v01 = acc[mi][ni][1] + Us[rA * 256 + j0 + 1];
            float v10 = acc[mi][ni][2] + Us[(rA + 8) * 256 + j0];
            float v11 = acc[mi][ni][3] + Us[(rA + 8) * 256 + j0 + 1];
            rs[mi][0] += tanhfast(v00) * Va[j0] + tanhfast(v01) * Va[j0 + 1];
            rs[mi][1] += tanhfast(v10) * Va[j0] + tanhfast(v11) * Va[j0 + 1];
        }
    }
    #pragma unroll
    for (int mi = 0; mi < 2; mi++)
        #pragma unroll
        for (int hh = 0; hh < 2; hh++) {
            rs[mi][hh] += __shfl_xor_sync(0xffffffff, rs[mi][hh], 1);
            rs[mi][hh] += __shfl_xor_sync(0xffffffff, rs[mi][hh], 2);
        }
    if (tq == 0) {
        float vb = va_b[0];
        #pragma unroll
        for (int mi = 0; mi < 2; mi++)
            #pragma unroll
            for (int hh = 0; hh < 2; hh++) {
                int row = rowbase + wm * 32 + mi * 16 + g + hh * 8;
                g_scores[(size_t)row * 8 + hg * 4 + wn] = rs[mi][hh] + vb;
            }
    }
}

// ---------------- K2a: per-(b,h) max and sum(exp) ----------------------------
__global__ void k_stats() {
    __shared__ float red[256];
    int bh = blockIdx.x, t = threadIdx.x;
    float v[16];
    float mx = -1e30f;
    #pragma unroll
    for (int i = 0; i < 16; i++) {
        v[i] = g_scores[(size_t)(i * 256 + t) * 256 + bh];
        mx = fmaxf(mx, v[i]);
    }
    red[t] = mx; __syncthreads();
    for (int s = 128; s > 0; s >>= 1) {
        if (t < s) red[t] = fmaxf(red[t], red[t + s]);
        __syncthreads();
    }
    mx = red[0]; __syncthreads();
    float sum = 0.f;
    #pragma unroll
    for (int i = 0; i < 16; i++) sum += __expf(v[i] - mx);
    red[t] = sum; __syncthreads();
    for (int s = 128; s > 0; s >>= 1) {
        if (t < s) red[t] += red[t + s];
        __syncthreads();
    }
    if (t == 0) { g_smax[bh] = mx; g_ssum[bh] = red[0]; }
}

// ---------------- K2b: normalize -> weights + head-mean output --------------
__global__ void k_weights(float* __restrict__ out_w) {
    int idx = blockIdx.x * 256 + threadIdx.x;   // (p*32+b) < 131072
    int b = idx & 31;
    float sc[8];
    *reinterpret_cast<float4*>(&sc[0]) = *reinterpret_cast<const float4*>(&g_scores[(size_t)idx * 8]);
    *reinterpret_cast<float4*>(&sc[4]) = *reinterpret_cast<const float4*>(&g_scores[(size_t)idx * 8 + 4]);
    float w[8], tot = 0.f;
    #pragma unroll
    for (int h = 0; h < 8; h++) {
        float m = g_smax[b * 8 + h], s = g_ssum[b * 8 + h];
        w[h] = __fdividef(__expf(sc[h] - m), s);
        tot += w[h];
    }
    *reinterpret_cast<float4*>(&g_weights[(size_t)idx * 8])     = *reinterpret_cast<float4*>(&w[0]);
    *reinterpret_cast<float4*>(&g_weights[(size_t)idx * 8 + 4]) = *reinterpret_cast<float4*>(&w[4]);
    out_w[idx] = tot * 0.125f;
}

// ---------------- K3: partial xbar = sum_p w[p,b,h]*X[p,b,f] -----------------
__global__ void k_xbar(const float* __restrict__ X) {
    __shared__ float ws[256 * 8];
    int b = blockIdx.x, fc = blockIdx.y, pc = blockIdx.z;
    int tid = threadIdx.x;                 // 256
    int f = fc * 256 + tid;
    int p0 = pc * 256;
    #pragma unroll
    for (int it = 0; it < 2; it++) {
        int fid = tid + 256 * it;          // 0..511 float4s
        int pp = fid >> 1, h4 = (fid & 1) * 4;
        *reinterpret_cast<float4*>(&ws[pp * 8 + h4]) =
            *reinterpret_cast<const float4*>(&g_weights[((size_t)(p0 + pp) * BB + b) * 8 + h4]);
    }
    __syncthreads();
    float acc[8];
    #pragma unroll
    for (int h = 0; h < 8; h++) acc[h] = 0.f;
    for (int p = 0; p < 256; p++) {
        float x = X[((size_t)(p0 + p) * BB + b) * FEAT + f];
        float4 w0 = *reinterpret_cast<float4*>(&ws[p * 8]);
        float4 w1 = *reinterpret_cast<float4*>(&ws[p * 8 + 4]);
        acc[0] += w0.x * x; acc[1] += w0.y * x; acc[2] += w0.z * x; acc[3] += w0.w * x;
        acc[4] += w1.x * x; acc[5] += w1.y * x; acc[6] += w1.z * x; acc[7] += w1.w * x;
    }
    #pragma unroll
    for (int h = 0; h < 8; h++)
        g_partial[(((size_t)pc * BB + b) * NH + h) * FEAT + f] = acc[h];
}

// ---------------- K4: context = xbar @ Wa_slice + Wa_b -----------------------
__global__ void k_context(const float* __restrict__ Wa, const float* __restrict__ Wa_b,
                          float* __restrict__ out) {
    __shared__ float xb[NH * FEAT];        // 16KB
    int b = blockIdx.x, t = threadIdx.x;   // 512 threads
    for (int i = t; i < NH * FEAT; i += 512) {
        float s = 0.f;
        #pragma unroll
        for (int pc = 0; pc < PCH; pc++) s += g_partial[((size_t)pc * BB + b) * (NH * FEAT) + i];
        xb[i] = s;
    }
    __syncthreads();
    int h = t >> 6;
    float acc = Wa_b[t];
    for (int k = 0; k < FEAT; k++) acc += xb[h * FEAT + k] * Wa[k * ATTN + t];
    out[b * ATTN + t] = acc;
}

// ---------------- launch -----------------------------------------------------
extern "C" void kernel_launch(void* const* d_in, const int* in_sizes, int n_in,
                              void* d_out, int out_size) {
    const float* lh    = (const float*)d_in[0];
    const float* X     = (const float*)d_in[1];
    const float* Wa_w  = (const float*)d_in[2];
    const float* Wa_b  = (const float*)d_in[3];
    const float* Ua_w  = (const float*)d_in[4];
    const float* Ua_b  = (const float*)d_in[5];
    const float* Wa2_w = (const float*)d_in[6];
    const float* Wa2_b = (const float*)d_in[7];
    const float* Ua2_w = (const float*)d_in[8];
    const float* Ua2_b = (const float*)d_in[9];
    const float* va_w  = (const float*)d_in[10];
    const float* va_b  = (const float*)d_in[11];
    float* out = (float*)d_out;            // [0,16384): context, [16384,147456): weight

    static int smem_set = 0;
    if (!smem_set) {
        cudaFuncSetAttribute(k_scores2, cudaFuncAttributeMaxDynamicSharedMemorySize, SMEM_TOTAL);
        smem_set = 1;
    }

    k_prep_u<<<BB, 512>>>(lh, Ua_w, Ua_b, Ua2_w, Ua2_b, Wa_b, Wa2_w, Wa2_b);
    k_prep_B<<<FEAT, 512>>>(Wa_w, Wa2_w);
    k_scores2<<<dim3(2, MROWS / 128), 512, SMEM_TOTAL>>>(X, va_w, va_b);
    k_stats<<<BB * NH, 256>>>();
    k_weights<<<MROWS / 256, 256>>>(out + BB * ATTN);
    k_xbar<<<dim3(BB, 2, PCH), 256>>>(X);
    k_context<<<BB, 512>>>(Wa_w, Wa_b, out);
}